// round 6
// baseline (speedup 1.0000x reference)
#include <cuda_runtime.h>

#define T_STEPS 4096
#define BATCH 64
#define IN_DIM 4
#define HID 256
#define OUT_DIM 2

// hidden-state history for the output head: [T, B, H] fp32 = 268 MB scratch
__device__ float g_hs[(size_t)T_STEPS * BATCH * HID];

__device__ __forceinline__ void fma2(unsigned long long &acc,
                                     unsigned long long a,
                                     unsigned long long b) {
    asm("fma.rn.f32x2 %0, %1, %2, %0;" : "+l"(acc) : "l"(a), "l"(b));
}

__device__ __forceinline__ float2 unpack2(unsigned long long v) {
    float2 f;
    asm("mov.b64 {%0, %1}, %2;" : "=f"(f.x), "=f"(f.y) : "l"(v));
    return f;
}

__device__ __forceinline__ unsigned int smem_u32(const void* p) {
    unsigned int a;
    asm("{ .reg .u64 t; cvta.to.shared.u64 t, %1; cvt.u32.u64 %0, t; }"
        : "=r"(a) : "l"(p));
    return a;
}

__device__ __forceinline__ unsigned int mapa_peer(unsigned int laddr,
                                                  unsigned int peer) {
    unsigned int r;
    asm("mapa.shared::cluster.u32 %0, %1, %2;" : "=r"(r) : "r"(laddr), "r"(peer));
    return r;
}

// 128-MAC dot product: 64 packed f32x2 FMAs against broadcast LDS.128 reads
__device__ __forceinline__ float dot128(const unsigned long long* __restrict__ wh,
                                        const float* __restrict__ hsrc) {
    const ulonglong2* h2 = (const ulonglong2*)hsrc;
    unsigned long long a0 = 0ull, a1 = 0ull, a2 = 0ull, a3 = 0ull;
#pragma unroll
    for (int m = 0; m < 32; m += 2) {
        ulonglong2 hm0 = h2[m];
        fma2(a0, wh[2 * m],     hm0.x);
        fma2(a1, wh[2 * m + 1], hm0.y);
        ulonglong2 hm1 = h2[m + 1];
        fma2(a2, wh[2 * m + 2], hm1.x);
        fma2(a3, wh[2 * m + 3], hm1.y);
    }
    float2 f0 = unpack2(a0), f1 = unpack2(a1);
    float2 f2 = unpack2(a2), f3 = unpack2(a3);
    return ((f0.x + f0.y) + (f1.x + f1.y)) + ((f2.x + f2.y) + (f3.x + f3.y));
}

// spin until all 4 producer-warp flags reach `want`, then acquire-fence.
// Flags live in LOCAL smem (remote CTA wrote them) -> cheap LDS.128 polls.
__device__ __forceinline__ void poll4_acquire(unsigned int addr, unsigned int want) {
    unsigned int f0, f1, f2, f3;
    do {
        asm volatile("ld.volatile.shared.v4.u32 {%0,%1,%2,%3}, [%4];"
                     : "=r"(f0), "=r"(f1), "=r"(f2), "=r"(f3) : "r"(addr));
    } while (f0 < want || f1 < want || f2 < want || f3 < want);
    // fence-fence sync with the producers' st.release flags
    asm volatile("fence.acq_rel.cluster;" ::: "memory");
}

// producer warp: 32 data floats already stored via st.shared::cluster;
// publish with a single release-store of the step counter.
__device__ __forceinline__ void ship_flag(unsigned int raddr_flag, unsigned int val,
                                          bool lane0) {
    __syncwarp();   // all lanes' data stores ordered before the flag
    if (lane0)
        asm volatile("st.release.cluster.shared::cluster.u32 [%0], %1;"
                     :: "r"(raddr_flag), "r"(val) : "memory");
}

// ---------------------------------------------------------------------------
// Recurrence, K-split, TWO batches per 2-CTA cluster, FLAG-based exchange.
// Cluster c = batches (2c, 2c+1). CTA rank r owns k-range [128r,+128) of h
// and finalizes outputs j in the same range for both batches with the SAME
// register-resident weights Wh[j][k-range] (64 f32x2 regs/thread).
//   warps 4..7 (hi-wid, issue priority): compute peer-destined partials for
//       A then B; each warp ships 32 floats via st.shared::cluster and
//       publishes with ONE st.release.cluster flag = t+1.
//   warps 0..3: local partials for A and B (+xi+bias); spin on local flag
//       words (plain volatile LDS.128) + one fence.acq_rel.cluster; add
//       incoming partial, tanh, store h + stream g_hs.
// One __syncthreads per iteration (local h handoff). No cluster barrier,
// no mbarrier in the loop. Double-buffer reuse (t -> t+2) is safe by the
// causality chain through the recurrence (peer consumed buf[t&1] strictly
// before our t+2 partials can exist).
// ---------------------------------------------------------------------------
__global__ void __launch_bounds__(256, 1) __cluster_dims__(2, 1, 1)
elman_recurrence(const float* __restrict__ input,
                 const float* __restrict__ Wi,
                 const float* __restrict__ bi,
                 const float* __restrict__ Wh,
                 const float* __restrict__ bh) {
    __shared__ __align__(16) float hA[2][128], hB[2][128];  // local h halves
    __shared__ __align__(16) float pA[2][128], pB[2][128];  // incoming partials
    __shared__ __align__(16) unsigned int fA[2][4], fB[2][4]; // incoming flags

    const int tid  = threadIdx.x;
    const int rank = blockIdx.x & 1;
    const int c    = blockIdx.x >> 1;
    const int bA   = 2 * c;
    const int bB   = 2 * c + 1;
    const unsigned int peer = rank ^ 1;
    const bool is_local = (tid < 128);          // warps 0-3 = finalizers
    const int  li = tid & 127;
    const int  w  = li >> 5;                    // warp-in-role (0..3)
    const bool lane0 = ((tid & 31) == 0);

    const int j_out = (is_local ? 128 * rank : 128 * (1 - rank)) + li;

    // --- loop-invariant weights Wh[j_out][128*rank .. +128) in registers ---
    unsigned long long wh[64];
    {
        const ulonglong2* wsrc =
            (const ulonglong2*)(Wh + (size_t)j_out * HID + rank * 128);
#pragma unroll
        for (int m = 0; m < 32; ++m) {
            ulonglong2 v = __ldg(wsrc + m);
            wh[2 * m]     = v.x;
            wh[2 * m + 1] = v.y;
        }
    }

    // --- finalizer constants (same Wi row / bias for both batches) ---
    float4 wi4 = make_float4(0.f, 0.f, 0.f, 0.f);
    float  cb  = 0.f;
    if (is_local) {
        wi4 = __ldg((const float4*)(Wi + (size_t)j_out * IN_DIM));
        cb  = __ldg(bi + j_out) + __ldg(bh + j_out);
    }

    // --- producer remote addresses: peer pbuf slots + peer flag words ---
    unsigned int r_pA[2], r_pB[2], r_fA[2], r_fB[2];
    if (!is_local) {
#pragma unroll
        for (int s = 0; s < 2; ++s) {
            r_pA[s] = mapa_peer(smem_u32(&pA[s][li]), peer);
            r_pB[s] = mapa_peer(smem_u32(&pB[s][li]), peer);
            r_fA[s] = mapa_peer(smem_u32(&fA[s][w]), peer);
            r_fB[s] = mapa_peer(smem_u32(&fB[s][w]), peer);
        }
    }
    const unsigned int l_fA0 = smem_u32(&fA[0][0]);
    const unsigned int l_fA1 = smem_u32(&fA[1][0]);
    const unsigned int l_fB0 = smem_u32(&fB[0][0]);
    const unsigned int l_fB1 = smem_u32(&fB[1][0]);

    // --- init: zero flags and h0 ---
    if (tid < 16) ((unsigned int*)fA)[tid & 7] = 0u, ((unsigned int*)fB)[tid & 7] = 0u;
    if (is_local) { hA[0][li] = 0.f; hB[0][li] = 0.f; }
    __syncthreads();
    // both CTAs' flags/h must be visible before any remote traffic
    asm volatile("barrier.cluster.arrive.aligned;" ::: "memory");
    asm volatile("barrier.cluster.wait.aligned;" ::: "memory");

    // prefetch xi for t=0 (finalizers)
    float4 xinA = make_float4(0.f, 0.f, 0.f, 0.f);
    float4 xinB = xinA;
    if (is_local) {
        xinA = __ldg((const float4*)(input + (size_t)bA * IN_DIM));
        xinB = __ldg((const float4*)(input + (size_t)bB * IN_DIM));
    }

    float* hsA = g_hs + (size_t)bA * HID + (size_t)j_out;
    float* hsB = g_hs + (size_t)bB * HID + (size_t)j_out;

    for (int t = 0; t < T_STEPS; ++t) {
        const int cur = t & 1;
        const unsigned int stamp = (unsigned int)t + 1u;

        if (!is_local) {
            // ---- producers: ship A early (transit overlaps everything) ----
            float partA = dot128(wh, hA[cur]);
            asm volatile("st.shared::cluster.f32 [%0], %1;"
                         :: "r"(r_pA[cur]), "f"(partA) : "memory");
            ship_flag(r_fA[cur], stamp, lane0);

            float partB = dot128(wh, hB[cur]);
            asm volatile("st.shared::cluster.f32 [%0], %1;"
                         :: "r"(r_pB[cur]), "f"(partB) : "memory");
            ship_flag(r_fB[cur], stamp, lane0);
        } else {
            // ---- finalizers: both local dots BEFORE any wait ----
            float4 xnA = xinA, xnB = xinB;
            if (t + 1 < T_STEPS) {
                xnA = __ldg((const float4*)(input +
                            ((size_t)(t + 1) * BATCH + bA) * IN_DIM));
                xnB = __ldg((const float4*)(input +
                            ((size_t)(t + 1) * BATCH + bB) * IN_DIM));
            }

            float preA = dot128(wh, hA[cur]) + xinA.x * wi4.x + xinA.y * wi4.y +
                         xinA.z * wi4.z + xinA.w * wi4.w + cb;
            float preB = dot128(wh, hB[cur]) + xinB.x * wi4.x + xinB.y * wi4.y +
                         xinB.z * wi4.z + xinB.w * wi4.w + cb;

            // A: spin on local flags, acquire, finalize
            poll4_acquire(cur ? l_fA1 : l_fA0, stamp);
            float hnA = tanhf(preA + pA[cur][li]);
            hA[cur ^ 1][li] = hnA;
            hsA[(size_t)t * (BATCH * HID)] = hnA;

            // B: same
            poll4_acquire(cur ? l_fB1 : l_fB0, stamp);
            float hnB = tanhf(preB + pB[cur][li]);
            hB[cur ^ 1][li] = hnB;
            hsB[(size_t)t * (BATCH * HID)] = hnB;

            xinA = xnA;
            xinB = xnB;
        }

        // local h handoff to producers (drains STS; orders hA/hB[nxt])
        __syncthreads();
    }

    // keep cluster alive until the peer consumed our last remote stores
    asm volatile("barrier.cluster.arrive.aligned;" ::: "memory");
    asm volatile("barrier.cluster.wait.aligned;" ::: "memory");
}

// ---------------------------------------------------------------------------
// Output head: out[t,b,:] = tanh(hs[t,b,:] @ Wf^T + bf). One warp per row,
// grid-stride; memory-bound (streams 268 MB of hs at ~67% of HBM peak).
// ---------------------------------------------------------------------------
__global__ void __launch_bounds__(256)
elman_head(const float* __restrict__ Wf,
           const float* __restrict__ bf,
           float* __restrict__ out) {
    const int lane   = threadIdx.x & 31;
    const int gwarp  = (blockIdx.x * blockDim.x + threadIdx.x) >> 5;
    const int nwarps = (gridDim.x * blockDim.x) >> 5;

    const float bf0 = __ldg(bf + 0);
    const float bf1 = __ldg(bf + 1);

    const float4* wf0p = (const float4*)(Wf) + lane * 2;
    const float4* wf1p = (const float4*)(Wf + HID) + lane * 2;
    const float4 w00 = __ldg(wf0p), w01 = __ldg(wf0p + 1);
    const float4 w10 = __ldg(wf1p), w11 = __ldg(wf1p + 1);

    const int nrows = T_STEPS * BATCH;
    for (int row = gwarp; row < nrows; row += nwarps) {
        const float4* h = (const float4*)(g_hs + (size_t)row * HID) + lane * 2;
        float4 h0 = h[0], h1 = h[1];
        float s0 = h0.x * w00.x + h0.y * w00.y + h0.z * w00.z + h0.w * w00.w +
                   h1.x * w01.x + h1.y * w01.y + h1.z * w01.z + h1.w * w01.w;
        float s1 = h0.x * w10.x + h0.y * w10.y + h0.z * w10.z + h0.w * w10.w +
                   h1.x * w11.x + h1.y * w11.y + h1.z * w11.z + h1.w * w11.w;
#pragma unroll
        for (int o = 16; o; o >>= 1) {
            s0 += __shfl_xor_sync(0xffffffffu, s0, o);
            s1 += __shfl_xor_sync(0xffffffffu, s1, o);
        }
        if (lane == 0) {
            out[(size_t)row * OUT_DIM + 0] = tanhf(s0 + bf0);
            out[(size_t)row * OUT_DIM + 1] = tanhf(s1 + bf1);
        }
    }
}

extern "C" void kernel_launch(void* const* d_in, const int* in_sizes, int n_in,
                              void* d_out, int out_size) {
    // metadata order: input, target, Wi, bi, Wh, bh, Wf, bf
    const float* input = (const float*)d_in[0];
    const float* Wi = (const float*)d_in[2];
    const float* bi = (const float*)d_in[3];
    const float* Wh = (const float*)d_in[4];
    const float* bh = (const float*)d_in[5];
    const float* Wf = (const float*)d_in[6];
    const float* bf = (const float*)d_in[7];
    float* out = (float*)d_out;

    // 32 clusters x 2 CTAs, 2 batches per cluster
    elman_recurrence<<<BATCH, 256>>>(input, Wi, bi, Wh, bh);
    elman_head<<<2048, 256>>>(Wf, bf, out);
}

// round 7
// speedup vs baseline: 2.0482x; 2.0482x over previous
#include <cuda_runtime.h>

#define T_STEPS 4096
#define BATCH 64
#define IN_DIM 4
#define HID 256
#define OUT_DIM 2
#define HALF 128
#define HSTRIDE 132   // 128 floats + 4-float pad: half-1 base lands 4 banks away

// hidden-state history for the output head: [T, B, H] fp32 = 268 MB scratch
__device__ float g_hs[(size_t)T_STEPS * BATCH * HID];

__device__ __forceinline__ void fma2(unsigned long long &acc,
                                     unsigned long long a,
                                     unsigned long long b) {
    asm("fma.rn.f32x2 %0, %1, %2, %0;" : "+l"(acc) : "l"(a), "l"(b));
}

__device__ __forceinline__ float2 unpack2(unsigned long long v) {
    float2 f;
    asm("mov.b64 {%0, %1}, %2;" : "=f"(f.x), "=f"(f.y) : "l"(v));
    return f;
}

__device__ __forceinline__ unsigned int smem_u32(const void* p) {
    unsigned int a;
    asm("{ .reg .u64 t; cvta.to.shared.u64 t, %1; cvt.u32.u64 %0, t; }"
        : "=r"(a) : "l"(p));
    return a;
}

__device__ __forceinline__ unsigned int mapa_peer(unsigned int laddr,
                                                  unsigned int peer) {
    unsigned int r;
    asm("mapa.shared::cluster.u32 %0, %1, %2;" : "=r"(r) : "r"(laddr), "r"(peer));
    return r;
}

// 128-MAC half-K dot product: 64 packed f32x2 FMAs, broadcast LDS.128 reads
__device__ __forceinline__ float dot128(const unsigned long long* __restrict__ wh,
                                        const float* __restrict__ hsrc) {
    const ulonglong2* h2 = (const ulonglong2*)hsrc;
    unsigned long long a0 = 0ull, a1 = 0ull, a2 = 0ull, a3 = 0ull;
#pragma unroll
    for (int m = 0; m < 32; m += 2) {
        ulonglong2 hm0 = h2[m];
        fma2(a0, wh[2 * m],     hm0.x);
        fma2(a1, wh[2 * m + 1], hm0.y);
        ulonglong2 hm1 = h2[m + 1];
        fma2(a2, wh[2 * m + 2], hm1.x);
        fma2(a3, wh[2 * m + 3], hm1.y);
    }
    float2 f0 = unpack2(a0), f1 = unpack2(a1);
    float2 f2 = unpack2(a2), f3 = unpack2(a3);
    return ((f0.x + f0.y) + (f1.x + f1.y)) + ((f2.x + f2.y) + (f3.x + f3.y));
}

// spin until all 4 peer-warp flags reach `want` (local SMEM poll, cheap),
// then a CTA-scope fence (NO cluster scope -> no CCTL.IVALL L1 flush).
__device__ __forceinline__ void poll4(unsigned int addr, unsigned int want) {
    unsigned int f0, f1, f2, f3;
    do {
        asm volatile("ld.volatile.shared.v4.u32 {%0,%1,%2,%3}, [%4];"
                     : "=r"(f0), "=r"(f1), "=r"(f2), "=r"(f3) : "r"(addr));
    } while (f0 < want || f1 < want || f2 < want || f3 < want);
    asm volatile("fence.acq_rel.cta;" ::: "memory");
}

// ---------------------------------------------------------------------------
// Recurrence, output-split across a 2-CTA cluster; cluster c = batch b.
// CTA rank r computes h outputs [128r, 128r+128). Thread pair (2j, 2j+1)
// computes output j: lane 2j+p accumulates K-half p with 64 f32x2 registers
// of Wh, pair-reduced by one shfl.xor(1).
// h is double-buffered in SMEM with a 4-float pad between halves; the local
// half is written directly, the remote half ARRIVES via the peer's pushes.
// KEY STRUCTURE (the fix for R1..R6):
//   - pushes happen AFTER __syncthreads: warps 4-7 re-read the fresh local
//     h half from SMEM and st.shared::cluster it to the peer, followed by a
//     per-warp st.release.cluster stamp flag. Their remote stores drain at
//     the NEXT step's BAR (~400cy later) -> drain cost ~0, transit hidden
//     under the next step's FMA.
//   - consumers poll monotonic stamp flags in LOCAL SMEM + fence.acq_rel.CTA
//     (no cluster-scope fence/barrier/mbarrier anywhere in the loop).
// ---------------------------------------------------------------------------
__global__ void __launch_bounds__(256, 1) __cluster_dims__(2, 1, 1)
elman_recurrence(const float* __restrict__ input,
                 const float* __restrict__ Wi,
                 const float* __restrict__ bi,
                 const float* __restrict__ Wh,
                 const float* __restrict__ bh) {
    __shared__ __align__(16) float hbuf[2][2 * HSTRIDE];    // [buf][phys 0..263]
    __shared__ __align__(16) unsigned int fl[2][4];         // incoming stamps

    const int tid  = threadIdx.x;
    const int rank = blockIdx.x & 1;
    const int b    = blockIdx.x >> 1;
    const unsigned int peer = rank ^ 1;
    const int jl = tid >> 1;                 // local output index 0..127
    const int p  = tid & 1;                  // K-half this lane accumulates
    const int jg = HALF * rank + jl;         // global output index

    // --- loop-invariant weights Wh[jg][128p .. 128p+128) in registers ---
    unsigned long long wh[64];
    {
        const ulonglong2* wsrc =
            (const ulonglong2*)(Wh + (size_t)jg * HID + p * HALF);
#pragma unroll
        for (int m = 0; m < 32; ++m) {
            ulonglong2 v = __ldg(wsrc + m);
            wh[2 * m]     = v.x;
            wh[2 * m + 1] = v.y;
        }
    }

    // --- per-output constants (both lanes of the pair hold them) ---
    const float4 wi4 = __ldg((const float4*)(Wi + (size_t)jg * IN_DIM));
    const float  cb  = __ldg(bi + jg) + __ldg(bh + jg);

    // --- pusher (warps 4-7) remote addresses ---
    unsigned int r_h[2], r_f[2];
    const int li = tid - 128;                // pushed slot 0..127 (tid>=128)
    if (tid >= 128) {
        const int w = (tid >> 5) - 4;        // pusher warp 0..3
#pragma unroll
        for (int s = 0; s < 2; ++s) {
            r_h[s] = mapa_peer(smem_u32(&hbuf[s][HSTRIDE * rank + li]), peer);
            r_f[s] = mapa_peer(smem_u32(&fl[s][w]), peer);
        }
    }
    const unsigned int l_f0 = smem_u32(&fl[0][0]);
    const unsigned int l_f1 = smem_u32(&fl[1][0]);

    // --- init: flags = 0, h0 = 0 (both buffers' both halves) ---
    if (tid < 8) ((unsigned int*)fl)[tid] = 0u;
    if (tid < 2 * HSTRIDE) { hbuf[0][tid] = 0.f; hbuf[1][tid] = 0.f; }
    __syncthreads();
    // one-time: peer must see our zeroed flags/h before any remote traffic
    asm volatile("barrier.cluster.arrive.aligned;" ::: "memory");
    asm volatile("barrier.cluster.wait.aligned;" ::: "memory");

    // prefetch xi for t=0
    float4 xin = __ldg((const float4*)(input + (size_t)b * IN_DIM));

    float* hsb = g_hs + (size_t)b * HID + (size_t)jg;

    for (int t = 0; t < T_STEPS; ++t) {
        const int cur = t & 1;
        const int nxt = cur ^ 1;

        // remote half of hbuf[cur] must carry stamp >= t (t=0 trivially passes)
        poll4(cur ? l_f1 : l_f0, (unsigned int)t);

        // prefetch next xi (off critical path)
        float4 xnext = xin;
        if (t + 1 < T_STEPS)
            xnext = __ldg((const float4*)(input +
                          ((size_t)(t + 1) * BATCH + b) * IN_DIM));

        // --- K-half dot product + pair reduction ---
        float part = dot128(wh, &hbuf[cur][HSTRIDE * p]);
        part += __shfl_xor_sync(0xffffffffu, part, 1);

        float hn = tanhf(part + xin.x * wi4.x + xin.y * wi4.y +
                         xin.z * wi4.z + xin.w * wi4.w + cb);

        if (p == 0) hbuf[nxt][HSTRIDE * rank + jl] = hn;   // local h_next
        else        hsb[(size_t)t * (BATCH * HID)] = hn;   // stream hs
        xin = xnext;

        // local visibility of hbuf[nxt] (only local STS pending -> cheap;
        // pushers' remote STS from step t-1 drained during this step's FMA)
        __syncthreads();

        // --- push fresh local h half to peer (overlaps next step's FMA) ---
        if (tid >= 128 && t + 1 < T_STEPS) {
            float v = hbuf[nxt][HSTRIDE * rank + li];
            asm volatile("st.shared::cluster.f32 [%0], %1;"
                         :: "r"(r_h[nxt]), "f"(v) : "memory");
            __syncwarp(0xffffffffu);
            if ((tid & 31) == 0)
                asm volatile("st.release.cluster.shared::cluster.u32 [%0], %1;"
                             :: "r"(r_f[nxt]), "r"((unsigned int)(t + 1)) : "memory");
        }
    }

    // keep cluster alive until the peer's last incoming stores are irrelevant
    asm volatile("barrier.cluster.arrive.aligned;" ::: "memory");
    asm volatile("barrier.cluster.wait.aligned;" ::: "memory");
}

// ---------------------------------------------------------------------------
// Output head: out[t,b,:] = tanh(hs[t,b,:] @ Wf^T + bf). One warp per row,
// grid-stride; memory-bound (streams 268 MB of hs at ~69% of HBM peak).
// ---------------------------------------------------------------------------
__global__ void __launch_bounds__(256)
elman_head(const float* __restrict__ Wf,
           const float* __restrict__ bf,
           float* __restrict__ out) {
    const int lane   = threadIdx.x & 31;
    const int gwarp  = (blockIdx.x * blockDim.x + threadIdx.x) >> 5;
    const int nwarps = (gridDim.x * blockDim.x) >> 5;

    const float bf0 = __ldg(bf + 0);
    const float bf1 = __ldg(bf + 1);

    const float4* wf0p = (const float4*)(Wf) + lane * 2;
    const float4* wf1p = (const float4*)(Wf + HID) + lane * 2;
    const float4 w00 = __ldg(wf0p), w01 = __ldg(wf0p + 1);
    const float4 w10 = __ldg(wf1p), w11 = __ldg(wf1p + 1);

    const int nrows = T_STEPS * BATCH;
    for (int row = gwarp; row < nrows; row += nwarps) {
        const float4* h = (const float4*)(g_hs + (size_t)row * HID) + lane * 2;
        float4 h0 = h[0], h1 = h[1];
        float s0 = h0.x * w00.x + h0.y * w00.y + h0.z * w00.z + h0.w * w00.w +
                   h1.x * w01.x + h1.y * w01.y + h1.z * w01.z + h1.w * w01.w;
        float s1 = h0.x * w10.x + h0.y * w10.y + h0.z * w10.z + h0.w * w10.w +
                   h1.x * w11.x + h1.y * w11.y + h1.z * w11.z + h1.w * w11.w;
#pragma unroll
        for (int o = 16; o; o >>= 1) {
            s0 += __shfl_xor_sync(0xffffffffu, s0, o);
            s1 += __shfl_xor_sync(0xffffffffu, s1, o);
        }
        if (lane == 0) {
            out[(size_t)row * OUT_DIM + 0] = tanhf(s0 + bf0);
            out[(size_t)row * OUT_DIM + 1] = tanhf(s1 + bf1);
        }
    }
}

extern "C" void kernel_launch(void* const* d_in, const int* in_sizes, int n_in,
                              void* d_out, int out_size) {
    // metadata order: input, target, Wi, bi, Wh, bh, Wf, bf
    const float* input = (const float*)d_in[0];
    const float* Wi = (const float*)d_in[2];
    const float* bi = (const float*)d_in[3];
    const float* Wh = (const float*)d_in[4];
    const float* bh = (const float*)d_in[5];
    const float* Wf = (const float*)d_in[6];
    const float* bf = (const float*)d_in[7];
    float* out = (float*)d_out;

    // 64 clusters x 2 CTAs, 1 batch per cluster
    elman_recurrence<<<2 * BATCH, 256>>>(input, Wi, bi, Wh, bh);
    elman_head<<<2048, 256>>>(Wf, bf, out);
}

// round 9
// speedup vs baseline: 2.4590x; 1.2006x over previous
#include <cuda_runtime.h>

#define T_STEPS 4096
#define BATCH 64
#define IN_DIM 4
#define HID 256
#define OUT_DIM 2
#define HALF 128
#define HPAD 132            // 128 floats + 4-float pad (keeps 16B alignment)
#define NBUF 4              // 4-deep h buffers: read t&3, write (t+1)&3, wipe (t+2)&3

// hidden-state history for the output head: [T, B, H] fp32 = 268 MB scratch
__device__ float g_hs[(size_t)T_STEPS * BATCH * HID];

__device__ __forceinline__ void fma2(unsigned long long &acc,
                                     unsigned long long a,
                                     unsigned long long b) {
    asm("fma.rn.f32x2 %0, %1, %2, %0;" : "+l"(acc) : "l"(a), "l"(b));
}

__device__ __forceinline__ float2 unpack2(unsigned long long v) {
    float2 f;
    asm("mov.b64 {%0, %1}, %2;" : "=f"(f.x), "=f"(f.y) : "l"(v));
    return f;
}

__device__ __forceinline__ unsigned int smem_u32(const void* p) {
    unsigned int a;
    asm("{ .reg .u64 t; cvta.to.shared.u64 t, %1; cvt.u32.u64 %0, t; }"
        : "=r"(a) : "l"(p));
    return a;
}

__device__ __forceinline__ unsigned int mapa_peer(unsigned int laddr,
                                                  unsigned int peer) {
    unsigned int r;
    asm("mapa.shared::cluster.u32 %0, %1, %2;" : "=r"(r) : "r"(laddr), "r"(peer));
    return r;
}

// 128-MAC dot with NaN-retry. Volatile 16B LDS so every retry re-reads SMEM.
// Slots not yet written by the peer hold NaN sentinels -> accumulator is NaN
// -> warp retries (warp-uniform via __any_sync; stable lanes just recompute).
// A non-NaN result proves every one of the 128 inputs is real data.
__device__ __forceinline__ float dot128_retry(const unsigned long long* __restrict__ wh,
                                              unsigned int a) {
    float part;
    unsigned int bad;
    do {
        unsigned long long c0 = 0ull, c1 = 0ull, c2 = 0ull, c3 = 0ull;
#pragma unroll
        for (int m = 0; m < 32; m += 2) {
            unsigned long long x0, x1, x2, x3;
            asm volatile("ld.volatile.shared.v2.u64 {%0, %1}, [%2];"
                         : "=l"(x0), "=l"(x1) : "r"(a + m * 16));
            asm volatile("ld.volatile.shared.v2.u64 {%0, %1}, [%2];"
                         : "=l"(x2), "=l"(x3) : "r"(a + m * 16 + 16));
            fma2(c0, wh[2 * m],     x0);
            fma2(c1, wh[2 * m + 1], x1);
            fma2(c2, wh[2 * m + 2], x2);
            fma2(c3, wh[2 * m + 3], x3);
        }
        float2 f0 = unpack2(c0), f1 = unpack2(c1);
        float2 f2 = unpack2(c2), f3 = unpack2(c3);
        part = ((f0.x + f0.y) + (f1.x + f1.y)) + ((f2.x + f2.y) + (f3.x + f3.y));
        // fast-math-immune NaN test via integer compare
        unsigned int v = __float_as_uint(part);
        bad = ((v & 0x7fffffffu) > 0x7f800000u) ? 1u : 0u;
    } while (__any_sync(0xffffffffu, bad));
    return part;
}

// ---------------------------------------------------------------------------
// Recurrence, output-split, 2-CTA cluster per batch; SENTINEL exchange.
// CTA rank r computes h outputs [128r,+128) — which is exactly k-half r of
// the next step's h. Pair (2j,2j+1): lane p accumulates k-half p (128 MACs,
// 64 f32x2 weight regs). Lane p==r reads the locally-written half; lane
// p==1-r reads the remote-landing half via the NaN-retry dot.
// Per step t: read hx[t&3], local-store + peer-push hn into hx[(t+1)&3],
// wipe hx[(t+2)&3] remote half to NaN. Wipes causally precede the peer's
// next writes to that buffer (anchored through BAR(t) + two DSMEM transits),
// so no timing assumption. NO flags, NO fences, NO cluster barrier in loop.
// ---------------------------------------------------------------------------
__global__ void __launch_bounds__(256, 1) __cluster_dims__(2, 1, 1)
elman_recurrence(const float* __restrict__ input,
                 const float* __restrict__ Wi,
                 const float* __restrict__ bi,
                 const float* __restrict__ Wh,
                 const float* __restrict__ bh) {
    // hx[buf][khalf][slot]; khalf==rank is locally written, 1-rank is remote
    __shared__ __align__(16) float hx[NBUF][2][HPAD];

    const int tid  = threadIdx.x;
    const int rank = blockIdx.x & 1;
    const int b    = blockIdx.x >> 1;
    const unsigned int peer = rank ^ 1;
    const int jl = tid >> 1;                // local output index 0..127
    const int p  = tid & 1;                 // k-half this lane accumulates
    const int jg = HALF * rank + jl;        // global output index

    // --- loop-invariant weights Wh[jg][128p .. +128) in registers ---
    unsigned long long wh[64];
    {
        const ulonglong2* wsrc =
            (const ulonglong2*)(Wh + (size_t)jg * HID + p * HALF);
#pragma unroll
        for (int m = 0; m < 32; ++m) {
            ulonglong2 v = __ldg(wsrc + m);
            wh[2 * m]     = v.x;
            wh[2 * m + 1] = v.y;
        }
    }

    const float4 wi4 = __ldg((const float4*)(Wi + (size_t)jg * IN_DIM));
    const float  cb  = __ldg(bi + jg) + __ldg(bh + jg);

    // --- per-buffer addresses ---
    unsigned int rd_a[NBUF];     // my read base: &hx[s][p][0]
    unsigned int r_h[NBUF];      // peer push target: peer's &hx[s][rank][jl]
    unsigned int wipe_a[NBUF];   // my wipe slot: &hx[s][1-rank][tid] (tid<128)
#pragma unroll
    for (int s = 0; s < NBUF; ++s) {
        rd_a[s] = smem_u32(&hx[s][p][0]);
        r_h[s]  = mapa_peer(smem_u32(&hx[s][rank][jl]), peer);
        wipe_a[s] = smem_u32(&hx[s][1 - rank][tid & 127]);
    }

    // --- init: buf0 = h0 = 0 (both halves); bufs 1..3 remote half = NaN ---
    if (tid < HPAD) {
        hx[0][0][tid] = 0.f;
        hx[0][1][tid] = 0.f;
#pragma unroll
        for (int s = 1; s < NBUF; ++s)
            ((unsigned int*)&hx[s][1 - rank][0])[tid] = 0x7fffffffu;
    }
    __syncthreads();
    // one-time: peer must see our init before its first pushes land
    asm volatile("barrier.cluster.arrive.aligned;" ::: "memory");
    asm volatile("barrier.cluster.wait.aligned;" ::: "memory");

    float4 xin = __ldg((const float4*)(input + (size_t)b * IN_DIM));
    float* hsb = g_hs + (size_t)b * HID + (size_t)jg;

    for (int t = 0; t < T_STEPS; ++t) {
        const int cur = t & 3;
        const int nxt = (t + 1) & 3;
        const int wb  = (t + 2) & 3;

        // wipe the buffer last read at t-2; peer writes it again at its t+1,
        // causally after all our step-t work (incl. this wipe) via BAR(t).
        if (tid < HALF)
            asm volatile("st.shared.u32 [%0], %1;"
                         :: "r"(wipe_a[wb]), "r"(0x7fffffffu) : "memory");

        // prefetch next xi (independent)
        float4 xnext = xin;
        if (t + 1 < T_STEPS)
            xnext = __ldg((const float4*)(input +
                          ((size_t)(t + 1) * BATCH + b) * IN_DIM));

        // dot over my k-half; remote lanes self-synchronize via NaN retry
        float part = dot128_retry(wh, rd_a[cur]);
        part += __shfl_xor_sync(0xffffffffu, part, 1);

        float hn = tanhf(part + xin.x * wi4.x + xin.y * wi4.y +
                         xin.z * wi4.z + xin.w * wi4.w + cb);

        if (p == rank) {
            hx[nxt][rank][jl] = hn;                      // local half store
        } else {
            asm volatile("st.shared::cluster.f32 [%0], %1;"  // push to peer
                         :: "r"(r_h[nxt]), "f"(hn) : "memory");
            hsb[(size_t)t * (BATCH * HID)] = hn;         // stream g_hs
        }
        xin = xnext;

        // orders: local-half stores + wipes vs next step's reads (intra-CTA)
        __syncthreads();
    }

    // keep SMEM alive until the peer's last in-flight pushes are irrelevant
    asm volatile("barrier.cluster.arrive.aligned;" ::: "memory");
    asm volatile("barrier.cluster.wait.aligned;" ::: "memory");
}

// ---------------------------------------------------------------------------
// Output head: out[t,b,:] = tanh(hs[t,b,:] @ Wf^T + bf). One warp per row,
// grid-stride; memory-bound (streams 268 MB of hs at ~68% of HBM peak).
// ---------------------------------------------------------------------------
__global__ void __launch_bounds__(256)
elman_head(const float* __restrict__ Wf,
           const float* __restrict__ bf,
           float* __restrict__ out) {
    const int lane   = threadIdx.x & 31;
    const int gwarp  = (blockIdx.x * blockDim.x + threadIdx.x) >> 5;
    const int nwarps = (gridDim.x * blockDim.x) >> 5;

    const float bf0 = __ldg(bf + 0);
    const float bf1 = __ldg(bf + 1);

    const float4* wf0p = (const float4*)(Wf) + lane * 2;
    const float4* wf1p = (const float4*)(Wf + HID) + lane * 2;
    const float4 w00 = __ldg(wf0p), w01 = __ldg(wf0p + 1);
    const float4 w10 = __ldg(wf1p), w11 = __ldg(wf1p + 1);

    const int nrows = T_STEPS * BATCH;
    for (int row = gwarp; row < nrows; row += nwarps) {
        const float4* h = (const float4*)(g_hs + (size_t)row * HID) + lane * 2;
        float4 h0 = h[0], h1 = h[1];
        float s0 = h0.x * w00.x + h0.y * w00.y + h0.z * w00.z + h0.w * w00.w +
                   h1.x * w01.x + h1.y * w01.y + h1.z * w01.z + h1.w * w01.w;
        float s1 = h0.x * w10.x + h0.y * w10.y + h0.z * w10.z + h0.w * w10.w +
                   h1.x * w11.x + h1.y * w11.y + h1.z * w11.z + h1.w * w11.w;
#pragma unroll
        for (int o = 16; o; o >>= 1) {
            s0 += __shfl_xor_sync(0xffffffffu, s0, o);
            s1 += __shfl_xor_sync(0xffffffffu, s1, o);
        }
        if (lane == 0) {
            out[(size_t)row * OUT_DIM + 0] = tanhf(s0 + bf0);
            out[(size_t)row * OUT_DIM + 1] = tanhf(s1 + bf1);
        }
    }
}

extern "C" void kernel_launch(void* const* d_in, const int* in_sizes, int n_in,
                              void* d_out, int out_size) {
    // metadata order: input, target, Wi, bi, Wh, bh, Wf, bf
    const float* input = (const float*)d_in[0];
    const float* Wi = (const float*)d_in[2];
    const float* bi = (const float*)d_in[3];
    const float* Wh = (const float*)d_in[4];
    const float* bh = (const float*)d_in[5];
    const float* Wf = (const float*)d_in[6];
    const float* bf = (const float*)d_in[7];
    float* out = (float*)d_out;

    // 64 clusters x 2 CTAs, 1 batch per cluster
    elman_recurrence<<<2 * BATCH, 256>>>(input, Wi, bi, Wh, bh);
    elman_head<<<2048, 256>>>(Wf, bf, out);
}

// round 10
// speedup vs baseline: 2.5648x; 1.0430x over previous
#include <cuda_runtime.h>

#define T_STEPS 4096
#define BATCH 64
#define IN_DIM 4
#define HID 256
#define OUT_DIM 2
#define HALF 128
#define HPAD 132            // 128 floats + 4-float pad (keeps 16B alignment)
#define NBUF 4              // read t&3, write (t+1)&3, wipe (t+2)&3

// hidden-state history for the output head: [T, B, H] fp32 = 268 MB scratch
__device__ float g_hs[(size_t)T_STEPS * BATCH * HID];

__device__ __forceinline__ void fma2(unsigned long long &acc,
                                     unsigned long long a,
                                     unsigned long long b) {
    asm("fma.rn.f32x2 %0, %1, %2, %0;" : "+l"(acc) : "l"(a), "l"(b));
}

__device__ __forceinline__ float2 unpack2(unsigned long long v) {
    float2 f;
    asm("mov.b64 {%0, %1}, %2;" : "=f"(f.x), "=f"(f.y) : "l"(v));
    return f;
}

__device__ __forceinline__ unsigned int smem_u32(const void* p) {
    unsigned int a;
    asm("{ .reg .u64 t; cvta.to.shared.u64 t, %1; cvt.u32.u64 %0, t; }"
        : "=r"(a) : "l"(p));
    return a;
}

__device__ __forceinline__ unsigned int mapa_peer(unsigned int laddr,
                                                  unsigned int peer) {
    unsigned int r;
    asm("mapa.shared::cluster.u32 %0, %1, %2;" : "=r"(r) : "r"(laddr), "r"(peer));
    return r;
}

// 128-MAC dot with NaN-retry. Volatile 16B LDS so each retry re-reads SMEM.
// Unwritten slots hold NaN sentinels -> accumulator NaN -> retry.
// Non-NaN result proves all 128 inputs are real (fresh) data.
__device__ __forceinline__ float dot128_retry(const unsigned long long* __restrict__ wh,
                                              unsigned int a) {
    float part;
    unsigned int bad;
    do {
        unsigned long long c0 = 0ull, c1 = 0ull, c2 = 0ull, c3 = 0ull;
#pragma unroll
        for (int m = 0; m < 32; m += 2) {
            unsigned long long x0, x1, x2, x3;
            asm volatile("ld.volatile.shared.v2.u64 {%0, %1}, [%2];"
                         : "=l"(x0), "=l"(x1) : "r"(a + m * 16));
            asm volatile("ld.volatile.shared.v2.u64 {%0, %1}, [%2];"
                         : "=l"(x2), "=l"(x3) : "r"(a + m * 16 + 16));
            fma2(c0, wh[2 * m],     x0);
            fma2(c1, wh[2 * m + 1], x1);
            fma2(c2, wh[2 * m + 2], x2);
            fma2(c3, wh[2 * m + 3], x3);
        }
        float2 f0 = unpack2(c0), f1 = unpack2(c1);
        float2 f2 = unpack2(c2), f3 = unpack2(c3);
        part = ((f0.x + f0.y) + (f1.x + f1.y)) + ((f2.x + f2.y) + (f3.x + f3.y));
        unsigned int v = __float_as_uint(part);          // fast-math-immune
        bad = ((v & 0x7fffffffu) > 0x7f800000u) ? 1u : 0u;
    } while (__any_sync(0xffffffffu, bad));
    return part;
}

// ---------------------------------------------------------------------------
// Recurrence, output-split, 2-CTA cluster per batch. FULLY BARRIER-FREE loop:
// every h slot is protected by NaN sentinels; readers self-synchronize via
// the retry dot. No __syncthreads, no fences, no flags, no cluster barrier
// inside the loop.
// CTA rank r computes outputs [128r,+128) == k-half r of next h. Pair
// (2j,2j+1): lane p accumulates k-half p (64 f32x2 weight regs, 128 MACs).
// Ownership discipline (per lane, per step t):
//   1. wipe  hx[(t+2)&3][p][j] = NaN   (the slot this lane reads; precedes,
//      in program order, everything that can cause its next write)
//   2. retry-dot over hx[t&3][p][*]
//   3. pair shfl, tanh
//   4. write hn: p==rank -> local store hx[(t+1)&3][rank][j]
//                p!=rank -> push to peer's hx[(t+1)&3][rank-of-peer][j]
//      (push also streams hn to g_hs)
// Skew bound: a warp at step t consumed all 256 step-t inputs, so every pair
// finished its step t-1 write => no warp lags >1 step => wiping the buffer
// last read at t-2 is safe (NBUF=4).
// ---------------------------------------------------------------------------
__global__ void __launch_bounds__(256, 1) __cluster_dims__(2, 1, 1)
elman_recurrence(const float* __restrict__ input,
                 const float* __restrict__ Wi,
                 const float* __restrict__ bi,
                 const float* __restrict__ Wh,
                 const float* __restrict__ bh) {
    // hx[buf][khalf][slot]; khalf==rank written locally, 1-rank by peer push
    __shared__ __align__(16) float hx[NBUF][2][HPAD];

    const int tid  = threadIdx.x;
    const int rank = blockIdx.x & 1;
    const int b    = blockIdx.x >> 1;
    const unsigned int peer = rank ^ 1;
    const int jl = tid >> 1;                // output index 0..127
    const int p  = tid & 1;                 // k-half this lane accumulates
    const int jg = HALF * rank + jl;        // global output index

    // --- loop-invariant weights Wh[jg][128p .. +128) in registers ---
    unsigned long long wh[64];
    {
        const ulonglong2* wsrc =
            (const ulonglong2*)(Wh + (size_t)jg * HID + p * HALF);
#pragma unroll
        for (int m = 0; m < 32; ++m) {
            ulonglong2 v = __ldg(wsrc + m);
            wh[2 * m]     = v.x;
            wh[2 * m + 1] = v.y;
        }
    }

    const float4 wi4 = __ldg((const float4*)(Wi + (size_t)jg * IN_DIM));
    const float  cb  = __ldg(bi + jg) + __ldg(bh + jg);

    // --- per-buffer addresses ---
    unsigned int rd_a[NBUF];     // read base:  &hx[s][p][0]
    unsigned int wipe_a[NBUF];   // wipe slot:  &hx[s][p][jl] (this lane's read slot)
    unsigned int wr_a[NBUF];     // local write: &hx[s][rank][jl]   (p==rank lanes)
    unsigned int r_h[NBUF];      // peer push:  peer's &hx[s][rank][jl] (p!=rank)
#pragma unroll
    for (int s = 0; s < NBUF; ++s) {
        rd_a[s]   = smem_u32(&hx[s][p][0]);
        wipe_a[s] = smem_u32(&hx[s][p][jl]);
        wr_a[s]   = smem_u32(&hx[s][rank][jl]);
        r_h[s]    = mapa_peer(smem_u32(&hx[s][rank][jl]), peer);
    }

    // --- init: buffer 0 = h0 = 0 (both halves); buffers 1..3 = all NaN ---
    if (tid < HPAD) {
        hx[0][0][tid] = 0.f;
        hx[0][1][tid] = 0.f;
#pragma unroll
        for (int s = 1; s < NBUF; ++s) {
            ((unsigned int*)&hx[s][0][0])[tid] = 0x7fffffffu;
            ((unsigned int*)&hx[s][1][0])[tid] = 0x7fffffffu;
        }
    }
    __syncthreads();
    // one-time: peer must observe our init before its first pushes land here
    asm volatile("barrier.cluster.arrive.aligned;" ::: "memory");
    asm volatile("barrier.cluster.wait.aligned;" ::: "memory");

    float4 xin = __ldg((const float4*)(input + (size_t)b * IN_DIM));
    float* hsb = g_hs + (size_t)b * HID + (size_t)jg;

    for (int t = 0; t < T_STEPS; ++t) {
        const int cur = t & 3;
        const int nxt = (t + 1) & 3;
        const int wb  = (t + 2) & 3;

        // 1. wipe my read slot in the buffer due for reuse (program order:
        //    precedes my write/push that enables its next producer)
        asm volatile("st.volatile.shared.u32 [%0], %1;"
                     :: "r"(wipe_a[wb]), "r"(0x7fffffffu) : "memory");

        // prefetch next xi (independent of everything)
        float4 xnext = xin;
        if (t + 1 < T_STEPS)
            xnext = __ldg((const float4*)(input +
                          ((size_t)(t + 1) * BATCH + b) * IN_DIM));

        // 2. dot over my k-half; NaN retry self-synchronizes with producers
        float part = dot128_retry(wh, rd_a[cur]);
        // 3. pair reduction + activation
        part += __shfl_xor_sync(0xffffffffu, part, 1);
        float hn = tanhf(part + xin.x * wi4.x + xin.y * wi4.y +
                         xin.z * wi4.z + xin.w * wi4.w + cb);

        // 4. publish h_next (data IS the signal)
        if (p == rank) {
            asm volatile("st.volatile.shared.u32 [%0], %1;"
                         :: "r"(wr_a[nxt]), "r"(__float_as_uint(hn)) : "memory");
        } else {
            asm volatile("st.shared::cluster.f32 [%0], %1;"
                         :: "r"(r_h[nxt]), "f"(hn) : "memory");
            hsb[(size_t)t * (BATCH * HID)] = hn;   // stream hs (off-path)
        }
        xin = xnext;
        // NO __syncthreads: no STS drain, no barrier latency
    }

    // keep SMEM alive until the peer's last in-flight pushes are irrelevant
    asm volatile("barrier.cluster.arrive.aligned;" ::: "memory");
    asm volatile("barrier.cluster.wait.aligned;" ::: "memory");
}

// ---------------------------------------------------------------------------
// Output head: out[t,b,:] = tanh(hs[t,b,:] @ Wf^T + bf). One warp per row,
// grid-stride; memory-bound (streams 268 MB of hs at ~68% of HBM peak).
// ---------------------------------------------------------------------------
__global__ void __launch_bounds__(256)
elman_head(const float* __restrict__ Wf,
           const float* __restrict__ bf,
           float* __restrict__ out) {
    const int lane   = threadIdx.x & 31;
    const int gwarp  = (blockIdx.x * blockDim.x + threadIdx.x) >> 5;
    const int nwarps = (gridDim.x * blockDim.x) >> 5;

    const float bf0 = __ldg(bf + 0);
    const float bf1 = __ldg(bf + 1);

    const float4* wf0p = (const float4*)(Wf) + lane * 2;
    const float4* wf1p = (const float4*)(Wf + HID) + lane * 2;
    const float4 w00 = __ldg(wf0p), w01 = __ldg(wf0p + 1);
    const float4 w10 = __ldg(wf1p), w11 = __ldg(wf1p + 1);

    const int nrows = T_STEPS * BATCH;
    for (int row = gwarp; row < nrows; row += nwarps) {
        const float4* h = (const float4*)(g_hs + (size_t)row * HID) + lane * 2;
        float4 h0 = h[0], h1 = h[1];
        float s0 = h0.x * w00.x + h0.y * w00.y + h0.z * w00.z + h0.w * w00.w +
                   h1.x * w01.x + h1.y * w01.y + h1.z * w01.z + h1.w * w01.w;
        float s1 = h0.x * w10.x + h0.y * w10.y + h0.z * w10.z + h0.w * w10.w +
                   h1.x * w11.x + h1.y * w11.y + h1.z * w11.z + h1.w * w11.w;
#pragma unroll
        for (int o = 16; o; o >>= 1) {
            s0 += __shfl_xor_sync(0xffffffffu, s0, o);
            s1 += __shfl_xor_sync(0xffffffffu, s1, o);
        }
        if (lane == 0) {
            out[(size_t)row * OUT_DIM + 0] = tanhf(s0 + bf0);
            out[(size_t)row * OUT_DIM + 1] = tanhf(s1 + bf1);
        }
    }
}

extern "C" void kernel_launch(void* const* d_in, const int* in_sizes, int n_in,
                              void* d_out, int out_size) {
    // metadata order: input, target, Wi, bi, Wh, bh, Wf, bf
    const float* input = (const float*)d_in[0];
    const float* Wi = (const float*)d_in[2];
    const float* bi = (const float*)d_in[3];
    const float* Wh = (const float*)d_in[4];
    const float* bh = (const float*)d_in[5];
    const float* Wf = (const float*)d_in[6];
    const float* bf = (const float*)d_in[7];
    float* out = (float*)d_out;

    // 64 clusters x 2 CTAs, 1 batch per cluster
    elman_recurrence<<<2 * BATCH, 256>>>(input, Wi, bi, Wh, bh);
    elman_head<<<2048, 256>>>(Wf, bf, out);
}